// round 4
// baseline (speedup 1.0000x reference)
#include <cuda_runtime.h>

#define DD     4096
#define KB     128
#define TROWS  16384

// Y stored transposed-by-4-rows: g_Yt[(t/4)*128 + k] = {y[t..t+3][k]}
__device__ float4 g_Yt[(TROWS / 4) * KB];   // 8 MB

// bijective swizzle that varies with bits [2:4] so staging (j = 4t+q) spreads
__device__ __forceinline__ int swz(int j) { return j ^ ((j >> 2) & 7); }

__device__ __forceinline__ void fma2(unsigned long long& d,
                                     unsigned long long a, unsigned long long b) {
    asm("fma.rn.f32x2 %0, %1, %2, %0;" : "+l"(d) : "l"(a), "l"(b));
}
__device__ __forceinline__ unsigned long long pack2(float q) {
    unsigned long long r;
    asm("mov.b64 %0, {%1, %1};" : "=l"(r) : "r"(__float_as_uint(q)));
    return r;
}

// ---------------------------------------------------------------------------
// K1: Y = bin-sums of x. 1024 thr, 2 CTAs/SM, 16 rows/CTA (4 batches of 4).
// Per-CTA perm build (match_any counting sort) -> no separate sort kernel.
// ---------------------------------------------------------------------------
#define K1_ROWS 16
#define K1_NBLK (TROWS / K1_ROWS)
#define K1_OFF_PERM 65536
#define K1_OFF_OFFS (K1_OFF_PERM + 8192)
#define K1_SMEM     (K1_OFF_OFFS + 4 * (KB + 1))

__global__ void __launch_bounds__(1024, 2)
k1_bins(const float* __restrict__ x, const int* __restrict__ assign) {
    extern __shared__ char smem[];
    float4*         s_x4   = (float4*)smem;                       // 64 KB
    unsigned short* s_cnt  = (unsigned short*)smem;               // overlay (build)
    unsigned short* s_perm = (unsigned short*)(smem + K1_OFF_PERM);
    int*            s_off  = (int*)(smem + K1_OFF_OFFS);
    __shared__ int  s_warp[32];

    const int tid = threadIdx.x, lane = tid & 31, w = tid >> 5;

    // ---- per-CTA perm build -------------------------------------------------
    int av[4];
    #pragma unroll
    for (int i = 0; i < 4; i++) av[i] = assign[tid + 1024 * i] & 127;

    #pragma unroll
    for (int u = 0; u < 8; u++) ((unsigned*)s_cnt)[tid + 1024 * u] = 0;
    __syncthreads();

    unsigned rank[4];
    #pragma unroll
    for (int i = 0; i < 4; i++) {
        unsigned m = __match_any_sync(0xffffffffu, av[i]);
        rank[i] = __popc(m & ((1u << lane) - 1u));
        if (rank[i] == 0)
            s_cnt[av[i] * 128 + (w + 32 * i)] = (unsigned short)__popc(m);
    }
    __syncthreads();

    // scan 16384 cells (bin-major), 16 cells/thread, two passes (reg-light)
    const int base = tid * 16;
    int sum = 0;
    #pragma unroll
    for (int u = 0; u < 16; u++) sum += s_cnt[base + u];
    int v = sum;
    #pragma unroll
    for (int d = 1; d < 32; d <<= 1) {
        int n = __shfl_up_sync(0xffffffffu, v, d);
        if (lane >= d) v += n;
    }
    if (lane == 31) s_warp[w] = v;
    __syncthreads();
    if (w == 0) {
        int t = s_warp[lane];
        #pragma unroll
        for (int d = 1; d < 32; d <<= 1) {
            int n = __shfl_up_sync(0xffffffffu, t, d);
            if (lane >= d) t += n;
        }
        s_warp[lane] = t;
    }
    __syncthreads();
    int run = v - sum + (w > 0 ? s_warp[w - 1] : 0);
    #pragma unroll
    for (int u = 0; u < 16; u++) {
        int c = s_cnt[base + u];
        s_cnt[base + u] = (unsigned short)run;
        run += c;
    }
    __syncthreads();

    if (tid < KB) s_off[tid] = s_cnt[tid * 128];
    if (tid == 0) s_off[KB]  = DD;

    #pragma unroll
    for (int i = 0; i < 4; i++) {
        int pos = (int)s_cnt[av[i] * 128 + (w + 32 * i)] + (int)rank[i];
        s_perm[pos] = (unsigned short)(tid + 1024 * i);
    }
    __syncthreads();   // s_cnt dead; s_x4 may now reuse the region

    // ---- main loop ----------------------------------------------------------
    const int bin = tid >> 3, sub = tid & 7;
    const int lo = s_off[bin] + sub, hi = s_off[bin + 1];
    const float4* x4 = (const float4*)x;
    const int t0 = blockIdx.x * K1_ROWS;

    #pragma unroll 1
    for (int b = 0; b < 4; b++) {
        const int tb = t0 + 4 * b;

        // stage rows tb..tb+3 transposed; conflict-free STS.64 (swz spreads q)
        {
            float4 r0 = x4[(size_t)(tb + 0) * 1024 + tid];
            float4 r1 = x4[(size_t)(tb + 1) * 1024 + tid];
            float2* d0 = (float2*)&s_x4[swz(4 * tid + 0)];
            float2* d1 = (float2*)&s_x4[swz(4 * tid + 1)];
            float2* d2 = (float2*)&s_x4[swz(4 * tid + 2)];
            float2* d3 = (float2*)&s_x4[swz(4 * tid + 3)];
            d0[0] = make_float2(r0.x, r1.x);
            d1[0] = make_float2(r0.y, r1.y);
            d2[0] = make_float2(r0.z, r1.z);
            d3[0] = make_float2(r0.w, r1.w);
            float4 r2 = x4[(size_t)(tb + 2) * 1024 + tid];
            float4 r3 = x4[(size_t)(tb + 3) * 1024 + tid];
            d0[1] = make_float2(r2.x, r3.x);
            d1[1] = make_float2(r2.y, r3.y);
            d2[1] = make_float2(r2.z, r3.z);
            d3[1] = make_float2(r2.w, r3.w);
        }
        __syncthreads();

        // bin gather: LDS.128 = 4 rows of feature j
        float4 acc = make_float4(0.f, 0.f, 0.f, 0.f);
        for (int s = lo; s < hi; s += 8) {
            float4 xv = s_x4[swz((int)s_perm[s])];
            acc.x += xv.x; acc.y += xv.y; acc.z += xv.z; acc.w += xv.w;
        }
        // reduce 8 sub-lanes (adjacent in warp) via shuffles
        #pragma unroll
        for (int d = 4; d >= 1; d >>= 1) {
            acc.x += __shfl_down_sync(0xffffffffu, acc.x, d);
            acc.y += __shfl_down_sync(0xffffffffu, acc.y, d);
            acc.z += __shfl_down_sync(0xffffffffu, acc.z, d);
            acc.w += __shfl_down_sync(0xffffffffu, acc.w, d);
        }
        if (sub == 0)
            g_Yt[(tb >> 2) * KB + bin] = acc;   // 4 lanes/warp: 64B contiguous
        __syncthreads();   // before next staging overwrites s_x4
    }
}

// ---------------------------------------------------------------------------
// K2: out[t,j] = (Y[t] @ QV)[a_j] + bias[j]. 512 thr, 2 CTAs/SM, 16 rows/CTA.
// QV kept in 64 KB smem (read conflict-free: lanes = consecutive kout).
// ---------------------------------------------------------------------------
#define K2_ROWS 16
#define K2_NBLK (TROWS / K2_ROWS)
#define K2_OFF_Y    65536
#define K2_OFF_PART (K2_OFF_Y + 4 * KB * 16)        // 4 groups * 128 float4
#define K2_OFF_QM   (K2_OFF_PART + 512 * 16)
#define K2_SMEM     (K2_OFF_QM + KB * 16)

__global__ void __launch_bounds__(512, 2)
k2_out(const float* __restrict__ qv, const int* __restrict__ assign,
       const float* __restrict__ bias, float* __restrict__ out) {
    extern __shared__ char smem[];
    float*  s_qv   = (float*)smem;                        // [128*128] 64 KB
    float4* s_y4   = (float4*)(smem + K2_OFF_Y);          // [4*128]
    float4* s_part = (float4*)(smem + K2_OFF_PART);       // [512]
    float4* s_qm4  = (float4*)(smem + K2_OFF_QM);         // [128]

    const int tid  = threadIdx.x;
    const int kout = tid & 127, c = tid >> 7;             // c in 0..3

    // QV -> smem (coalesced, once per CTA)
    #pragma unroll
    for (int u = 0; u < 8; u++)
        ((float4*)s_qv)[u * 512 + tid] = ((const float4*)qv)[u * 512 + tid];

    // output slots: 2 float4 slots per thread
    float4 biasr[2]; unsigned ar[2];
    #pragma unroll
    for (int s = 0; s < 2; s++) {
        int e4 = s * 512 + tid;
        biasr[s] = ((const float4*)bias)[e4];
        int4 a = ((const int4*)assign)[e4];
        ar[s] = (unsigned)(a.x & 127)
              | ((unsigned)(a.y & 127) << 8)
              | ((unsigned)(a.z & 127) << 16)
              | ((unsigned)(a.w & 127) << 24);
    }

    const int t0 = blockIdx.x * K2_ROWS;
    s_y4[tid] = g_Yt[(t0 >> 2) * KB + tid];   // 4 groups * 128, coalesced
    __syncthreads();

    float4* out4 = (float4*)out;

    #pragma unroll 1
    for (int g = 0; g < 4; g++) {
        const ulonglong2* sy2 = (const ulonglong2*)(s_y4 + g * KB);

        unsigned long long acc01 = 0ull, acc23 = 0ull;
        #pragma unroll
        for (int i = 0; i < 32; i++) {
            ulonglong2 yv = sy2[c * 32 + i];              // warp-broadcast
            unsigned long long qd = pack2(s_qv[(c * 32 + i) * KB + kout]);
            fma2(acc01, yv.x, qd);
            fma2(acc23, yv.y, qd);
        }
        s_part[tid] = make_float4(
            __uint_as_float((unsigned)acc01), __uint_as_float((unsigned)(acc01 >> 32)),
            __uint_as_float((unsigned)acc23), __uint_as_float((unsigned)(acc23 >> 32)));
        __syncthreads();

        if (tid < KB) {
            float4 t = s_part[tid];
            #pragma unroll
            for (int u = 1; u < 4; u++) {
                float4 p = s_part[tid + 128 * u];
                t.x += p.x; t.y += p.y; t.z += p.z; t.w += p.w;
            }
            s_qm4[tid] = t;
        }
        __syncthreads();

        // epilogue: 4 rows x 2 slots
        const int tg = t0 + 4 * g;
        #pragma unroll
        for (int s = 0; s < 2; s++) {
            unsigned a = ar[s];
            float4 q0 = s_qm4[a & 255];
            float4 q1 = s_qm4[(a >> 8)  & 255];
            float4 q2 = s_qm4[(a >> 16) & 255];
            float4 q3 = s_qm4[(a >> 24)];
            float4 bb = biasr[s];
            size_t rb = (size_t)tg * 1024 + s * 512 + tid;
            out4[rb]        = make_float4(q0.x + bb.x, q1.x + bb.y, q2.x + bb.z, q3.x + bb.w);
            out4[rb + 1024] = make_float4(q0.y + bb.x, q1.y + bb.y, q2.y + bb.z, q3.y + bb.w);
            out4[rb + 2048] = make_float4(q0.z + bb.x, q1.z + bb.y, q2.z + bb.z, q3.z + bb.w);
            out4[rb + 3072] = make_float4(q0.w + bb.x, q1.w + bb.y, q2.w + bb.z, q3.w + bb.w);
        }
        __syncthreads();   // s_part/s_qm4 reuse next group
    }
}

extern "C" void kernel_launch(void* const* d_in, const int* in_sizes, int n_in,
                              void* d_out, int out_size) {
    const float* x      = (const float*)d_in[0];
    const float* qv     = (const float*)d_in[1];
    const int*   assign = (const int*)d_in[2];
    const float* bias   = (const float*)d_in[3];
    float*       out    = (float*)d_out;

    (void)cudaFuncSetAttribute(k1_bins,
        cudaFuncAttributeMaxDynamicSharedMemorySize, K1_SMEM);
    (void)cudaFuncSetAttribute(k2_out,
        cudaFuncAttributeMaxDynamicSharedMemorySize, K2_SMEM);

    k1_bins<<<K1_NBLK, 1024, K1_SMEM>>>(x, assign);
    k2_out<<<K2_NBLK, 512, K2_SMEM>>>(qv, assign, bias, out);
}

// round 5
// speedup vs baseline: 1.4156x; 1.4156x over previous
#include <cuda_runtime.h>

#define DD     4096
#define KB     128
#define TROWS  16384

__device__ int            g_hist[KB];
__device__ int            g_offsets[KB + 1];
__device__ unsigned short g_perm[DD];
__device__ float4         g_Yt[(TROWS / 4) * KB];   // [t/4][k] -> y rows t..t+3

__device__ __forceinline__ int swz(int j) { return j ^ ((j >> 2) & 7); }

__device__ __forceinline__ void fma2(unsigned long long& d,
                                     unsigned long long a, unsigned long long b) {
    asm("fma.rn.f32x2 %0, %1, %2, %0;" : "+l"(d) : "l"(a), "l"(b));
}
__device__ __forceinline__ unsigned long long pack2(float q) {
    unsigned long long r;
    asm("mov.b64 %0, {%1, %1};" : "=l"(r) : "r"(__float_as_uint(q)));
    return r;
}

// ---------------------------------------------------------------------------
// k0a: bin histogram (int shared atomics -> deterministic)
// ---------------------------------------------------------------------------
__global__ void k0a(const int* __restrict__ assign) {
    __shared__ int h[KB];
    const int tid = threadIdx.x;
    if (tid < KB) h[tid] = 0;
    __syncthreads();
    #pragma unroll
    for (int i = 0; i < 4; i++)
        atomicAdd(&h[assign[tid + 1024 * i] & 127], 1);
    __syncthreads();
    if (tid < KB) g_hist[tid] = h[tid];
}

// ---------------------------------------------------------------------------
// k0b: 128 blocks x 32 threads; block b writes bin b's CSR segment (j asc.)
// ---------------------------------------------------------------------------
__global__ void k0b(const int* __restrict__ assign) {
    const int b = blockIdx.x, lane = threadIdx.x;

    int v = 0;
    for (int c = lane; c < b; c += 32) v += g_hist[c];
    #pragma unroll
    for (int d = 16; d >= 1; d >>= 1) v += __shfl_xor_sync(0xffffffffu, v, d);
    int base = v;                                // exclusive offset of bin b

    if (lane == 0) {
        g_offsets[b] = base;
        if (b == 0) g_offsets[KB] = DD;
    }
    for (int i = 0; i < DD / 32; i++) {
        int j = i * 32 + lane;
        bool hit = ((assign[j] & 127) == b);
        unsigned m = __ballot_sync(0xffffffffu, hit);
        if (hit) g_perm[base + __popc(m & ((1u << lane) - 1u))] = (unsigned short)j;
        base += __popc(m);
    }
}

// ---------------------------------------------------------------------------
// K1: Y = per-bin sums of x. 1024 thr, 16 rows/CTA (4 batches of 4 rows).
// Conflict-free transposed staging + prefetch + shuffle reduce.
// ---------------------------------------------------------------------------
#define K1_OFF_PERM 65536
#define K1_OFF_OFFS (K1_OFF_PERM + 8192)
#define K1_SMEM     (K1_OFF_OFFS + 4 * (KB + 1))

__global__ void __launch_bounds__(1024)
k1_bins(const float* __restrict__ x) {
    extern __shared__ char smem[];
    float4*         s_x4   = (float4*)smem;                       // 64 KB
    unsigned short* s_perm = (unsigned short*)(smem + K1_OFF_PERM); // pre-swz byte offs
    int*            s_off  = (int*)(smem + K1_OFF_OFFS);

    const int tid = threadIdx.x;

    // load perm, pre-swizzle, convert to byte offsets (two u16 per u32)
    for (int i = tid; i < DD / 2; i += 1024) {
        unsigned pr = ((const unsigned*)g_perm)[i];
        unsigned o0 = (unsigned)(swz((int)(pr & 0xffffu)) << 4);
        unsigned o1 = (unsigned)(swz((int)(pr >> 16)) << 4);
        ((unsigned*)s_perm)[i] = o0 | (o1 << 16);
    }
    if (tid <= KB) s_off[tid] = g_offsets[tid];

    const int bin = tid >> 3, sub = tid & 7;
    const float4* x4 = (const float4*)x;
    const int t0 = blockIdx.x * 16;

    float4 v0 = x4[(size_t)(t0 + 0) * 1024 + tid];
    float4 v1 = x4[(size_t)(t0 + 1) * 1024 + tid];
    float4 v2 = x4[(size_t)(t0 + 2) * 1024 + tid];
    float4 v3 = x4[(size_t)(t0 + 3) * 1024 + tid];

    __syncthreads();
    const int lo = s_off[bin] + sub, hi = s_off[bin + 1];

    #pragma unroll 1
    for (int b = 0; b < 4; b++) {
        const int tb = t0 + 4 * b;

        // transposed staging; swz makes all 4 STS.128 streams conflict-free
        s_x4[swz(4 * tid + 0)] = make_float4(v0.x, v1.x, v2.x, v3.x);
        s_x4[swz(4 * tid + 1)] = make_float4(v0.y, v1.y, v2.y, v3.y);
        s_x4[swz(4 * tid + 2)] = make_float4(v0.z, v1.z, v2.z, v3.z);
        s_x4[swz(4 * tid + 3)] = make_float4(v0.w, v1.w, v2.w, v3.w);
        __syncthreads();

        if (b < 3) {   // prefetch next batch; latency hidden under gather
            v0 = x4[(size_t)(tb + 4) * 1024 + tid];
            v1 = x4[(size_t)(tb + 5) * 1024 + tid];
            v2 = x4[(size_t)(tb + 6) * 1024 + tid];
            v3 = x4[(size_t)(tb + 7) * 1024 + tid];
        }

        // bin gather: LDS.128 = 4 rows of one feature
        float4 acc = make_float4(0.f, 0.f, 0.f, 0.f);
        const char* bx = (const char*)s_x4;
        for (int s = lo; s < hi; s += 8) {
            float4 xv = *(const float4*)(bx + s_perm[s]);
            acc.x += xv.x; acc.y += xv.y; acc.z += xv.z; acc.w += xv.w;
        }
        // reduce 8 sub-lanes to sub==0
        #pragma unroll
        for (int d = 4; d >= 1; d >>= 1) {
            acc.x += __shfl_down_sync(0xffffffffu, acc.x, d);
            acc.y += __shfl_down_sync(0xffffffffu, acc.y, d);
            acc.z += __shfl_down_sync(0xffffffffu, acc.z, d);
            acc.w += __shfl_down_sync(0xffffffffu, acc.w, d);
        }
        if (sub == 0) g_Yt[(tb >> 2) * KB + bin] = acc;
        __syncthreads();   // gather done before next staging overwrites s_x4
    }
}

// ---------------------------------------------------------------------------
// K2: out[t,j] = (Y[t] @ QV)[a_j] + bias[j]. 512 thr, 16 rows/CTA, 2 CTA/SM.
// Single hoisted matvec for all 4 row-groups; only 2 barriers per CTA.
// ---------------------------------------------------------------------------
#define K2_OFF_Y    65536
#define K2_OFF_PART (K2_OFF_Y + 8192)
#define K2_OFF_QM   (K2_OFF_PART + 32768)
#define K2_SMEM     (K2_OFF_QM + 8192)     // 64+8+32+8 = 112 KB

__global__ void __launch_bounds__(512, 2)
k2_out(const float* __restrict__ qv, const int* __restrict__ assign,
       const float* __restrict__ bias, float* __restrict__ out) {
    extern __shared__ char smem[];
    float*  s_qv   = (float*)smem;                      // [128*128]
    float4* s_y4   = (float4*)(smem + K2_OFF_Y);        // [4 groups][128]
    float4* s_part = (float4*)(smem + K2_OFF_PART);     // [g][c][kout]
    float4* s_qm   = (float4*)(smem + K2_OFF_QM);       // [g][kout]

    const int tid  = threadIdx.x;
    const int kout = tid & 127, c = tid >> 7;           // c uniform per warp

    #pragma unroll
    for (int u = 0; u < 8; u++)
        ((float4*)s_qv)[u * 512 + tid] = ((const float4*)qv)[u * 512 + tid];

    const int t0 = blockIdx.x * 16;
    s_y4[tid] = g_Yt[(t0 >> 2) * KB + tid];

    float4 biasr[2]; unsigned ar[2];
    #pragma unroll
    for (int s = 0; s < 2; s++) {
        int e4 = s * 512 + tid;
        biasr[s] = ((const float4*)bias)[e4];
        int4 a = ((const int4*)assign)[e4];
        ar[s] = (unsigned)(a.x & 127)
              | ((unsigned)(a.y & 127) << 8)
              | ((unsigned)(a.z & 127) << 16)
              | ((unsigned)(a.w & 127) << 24);
    }
    __syncthreads();

    // matvec for all 16 rows at once: acc[g] = rows 4g..4g+3 at column kout
    unsigned long long acc[8];
    #pragma unroll
    for (int i = 0; i < 8; i++) acc[i] = 0ull;
    const ulonglong2* sy2 = (const ulonglong2*)s_y4;
    #pragma unroll
    for (int i = 0; i < 32; i++) {
        unsigned long long qd = pack2(s_qv[(c * 32 + i) * KB + kout]); // conflict-free
        #pragma unroll
        for (int g = 0; g < 4; g++) {
            ulonglong2 yv = sy2[g * KB + c * 32 + i];    // warp-broadcast
            fma2(acc[2 * g],     yv.x, qd);
            fma2(acc[2 * g + 1], yv.y, qd);
        }
    }
    #pragma unroll
    for (int g = 0; g < 4; g++)
        s_part[g * 512 + c * 128 + kout] = make_float4(   // conflict-free STS.128
            __uint_as_float((unsigned)acc[2 * g]),
            __uint_as_float((unsigned)(acc[2 * g] >> 32)),
            __uint_as_float((unsigned)acc[2 * g + 1]),
            __uint_as_float((unsigned)(acc[2 * g + 1] >> 32)));
    __syncthreads();

    {   // reduce over c: thread handles (g=c, kout); conflict-free LDS.128
        float4 t = s_part[c * 512 + kout];
        #pragma unroll
        for (int u = 1; u < 4; u++) {
            float4 p = s_part[c * 512 + u * 128 + kout];
            t.x += p.x; t.y += p.y; t.z += p.z; t.w += p.w;
        }
        s_qm[c * KB + kout] = t;
    }
    __syncthreads();

    // barrier-free epilogue: 16 rows x 2 slots
    float4* out4 = (float4*)out;
    #pragma unroll
    for (int g = 0; g < 4; g++) {
        const float4* qm = s_qm + g * KB;
        #pragma unroll
        for (int s = 0; s < 2; s++) {
            unsigned a = ar[s];
            float4 q0 = qm[a & 255];
            float4 q1 = qm[(a >> 8)  & 255];
            float4 q2 = qm[(a >> 16) & 255];
            float4 q3 = qm[a >> 24];
            float4 bb = biasr[s];
            size_t rb = (size_t)(t0 + 4 * g) * 1024 + s * 512 + tid;
            out4[rb]        = make_float4(q0.x + bb.x, q1.x + bb.y, q2.x + bb.z, q3.x + bb.w);
            out4[rb + 1024] = make_float4(q0.y + bb.x, q1.y + bb.y, q2.y + bb.z, q3.y + bb.w);
            out4[rb + 2048] = make_float4(q0.z + bb.x, q1.z + bb.y, q2.z + bb.z, q3.z + bb.w);
            out4[rb + 3072] = make_float4(q0.w + bb.x, q1.w + bb.y, q2.w + bb.z, q3.w + bb.w);
        }
    }
}

extern "C" void kernel_launch(void* const* d_in, const int* in_sizes, int n_in,
                              void* d_out, int out_size) {
    const float* x      = (const float*)d_in[0];
    const float* qv     = (const float*)d_in[1];
    const int*   assign = (const int*)d_in[2];
    const float* bias   = (const float*)d_in[3];
    float*       out    = (float*)d_out;

    (void)cudaFuncSetAttribute(k1_bins,
        cudaFuncAttributeMaxDynamicSharedMemorySize, K1_SMEM);
    (void)cudaFuncSetAttribute(k2_out,
        cudaFuncAttributeMaxDynamicSharedMemorySize, K2_SMEM);

    k0a<<<1, 1024>>>(assign);
    k0b<<<KB, 32>>>(assign);
    k1_bins<<<TROWS / 16, 1024, K1_SMEM>>>(x);
    k2_out<<<TROWS / 16, 512, K2_SMEM>>>(qv, assign, bias, out);
}

// round 6
// speedup vs baseline: 1.4249x; 1.0066x over previous
#include <cuda_runtime.h>

#define DD     4096
#define KB     128
#define TROWS  16384

__device__ int            g_offsets[KB + 1];
__device__ unsigned short g_perm[DD];
__device__ float4         g_Yt[(TROWS / 4) * KB];   // [t/4][k] = y rows t..t+3

// swizzle matched to staging stride 8: j=8t+q -> low3 = q ^ (t&7): conflict-free
__device__ __forceinline__ int swz(int j) { return j ^ ((j >> 3) & 7); }

__device__ __forceinline__ void fma2(unsigned long long& d,
                                     unsigned long long a, unsigned long long b) {
    asm("fma.rn.f32x2 %0, %1, %2, %0;" : "+l"(d) : "l"(a), "l"(b));
}
__device__ __forceinline__ unsigned long long pack2(float q) {
    unsigned long long r;
    asm("mov.b64 %0, {%1, %1};" : "=l"(r) : "r"(__float_as_uint(q)));
    return r;
}

// ---------------------------------------------------------------------------
// k0: 128 blocks x 32 thr. Block b: offset = #{j: a_j < b} (one ballot pass),
// then writes bin b's CSR segment in ascending j. Deterministic.
// ---------------------------------------------------------------------------
__global__ void k0_build(const int* __restrict__ assign) {
    const int b = blockIdx.x, lane = threadIdx.x;

    int below = 0, base = 0;
    unsigned hitm[DD / 32 / 32];   // cache hit masks for the write pass? too big; redo pass
    (void)hitm;
    for (int i = 0; i < DD / 32; i++) {
        int a = assign[i * 32 + lane] & 127;
        below += (a < b);
    }
    #pragma unroll
    for (int d = 16; d >= 1; d >>= 1)
        below += __shfl_xor_sync(0xffffffffu, below, d);
    base = below;

    if (lane == 0) {
        g_offsets[b] = base;
        if (b == KB - 1) g_offsets[KB] = DD;
    }
    for (int i = 0; i < DD / 32; i++) {
        int j = i * 32 + lane;
        bool hit = ((assign[j] & 127) == b);
        unsigned m = __ballot_sync(0xffffffffu, hit);
        if (hit) g_perm[base + __popc(m & ((1u << lane) - 1u))] = (unsigned short)j;
        base += __popc(m);
    }
}

// ---------------------------------------------------------------------------
// K1: Y = per-bin sums. 512 thr, 2 CTAs/SM, 16 rows/CTA (4 batches of 4 rows).
// Thread stages columns j = 8*tid .. 8*tid+7 (matched swizzle, conflict-free).
// ---------------------------------------------------------------------------
#define K1_OFF_PERM 65536
#define K1_OFF_OFFS (K1_OFF_PERM + 8192)
#define K1_SMEM     (K1_OFF_OFFS + 4 * (KB + 1))

__global__ void __launch_bounds__(512, 2)
k1_bins(const float* __restrict__ x) {
    extern __shared__ char smem[];
    float4*         s_x4   = (float4*)smem;                         // 64 KB
    unsigned short* s_perm = (unsigned short*)(smem + K1_OFF_PERM); // pre-swz byte offs
    int*            s_off  = (int*)(smem + K1_OFF_OFFS);

    const int tid = threadIdx.x;

    for (int i = tid; i < DD / 2; i += 512) {
        unsigned pr = ((const unsigned*)g_perm)[i];
        unsigned o0 = (unsigned)(swz((int)(pr & 0xffffu)) << 4);
        unsigned o1 = (unsigned)(swz((int)(pr >> 16)) << 4);
        ((unsigned*)s_perm)[i] = o0 | (o1 << 16);
    }
    if (tid <= KB) s_off[tid] = g_offsets[tid];

    const int bin = tid >> 2, sub = tid & 3;
    const float4* x4 = (const float4*)x;
    const int t0 = blockIdx.x * 16;

    // v[r][p]: row t0+r, float4 columns 2*tid+p  (covers j = 8t..8t+7)
    float4 v[4][2];
    #pragma unroll
    for (int r = 0; r < 4; r++) {
        v[r][0] = x4[(size_t)(t0 + r) * 1024 + 2 * tid];
        v[r][1] = x4[(size_t)(t0 + r) * 1024 + 2 * tid + 1];
    }

    __syncthreads();
    const int lo = s_off[bin] + sub, hi = s_off[bin + 1];

    #pragma unroll 1
    for (int b = 0; b < 4; b++) {
        const int tb = t0 + 4 * b;

        // transposed staging: s_x4[swz(8t+q)] = {rows tb..tb+3 of feature 8t+q}
        #pragma unroll
        for (int p = 0; p < 2; p++) {
            s_x4[swz(8 * tid + 4 * p + 0)] = make_float4(v[0][p].x, v[1][p].x, v[2][p].x, v[3][p].x);
            s_x4[swz(8 * tid + 4 * p + 1)] = make_float4(v[0][p].y, v[1][p].y, v[2][p].y, v[3][p].y);
            s_x4[swz(8 * tid + 4 * p + 2)] = make_float4(v[0][p].z, v[1][p].z, v[2][p].z, v[3][p].z);
            s_x4[swz(8 * tid + 4 * p + 3)] = make_float4(v[0][p].w, v[1][p].w, v[2][p].w, v[3][p].w);
        }
        __syncthreads();

        if (b < 3) {   // prefetch next batch under the gather
            #pragma unroll
            for (int r = 0; r < 4; r++) {
                v[r][0] = x4[(size_t)(tb + 4 + r) * 1024 + 2 * tid];
                v[r][1] = x4[(size_t)(tb + 4 + r) * 1024 + 2 * tid + 1];
            }
        }

        // bin gather: LDS.128 = 4 rows of one feature; 4 subs per bin
        float4 acc = make_float4(0.f, 0.f, 0.f, 0.f);
        const char* bx = (const char*)s_x4;
        for (int s = lo; s < hi; s += 4) {
            float4 xv = *(const float4*)(bx + s_perm[s]);
            acc.x += xv.x; acc.y += xv.y; acc.z += xv.z; acc.w += xv.w;
        }
        #pragma unroll
        for (int d = 2; d >= 1; d >>= 1) {
            acc.x += __shfl_down_sync(0xffffffffu, acc.x, d);
            acc.y += __shfl_down_sync(0xffffffffu, acc.y, d);
            acc.z += __shfl_down_sync(0xffffffffu, acc.z, d);
            acc.w += __shfl_down_sync(0xffffffffu, acc.w, d);
        }
        if (sub == 0) g_Yt[(tb >> 2) * KB + bin] = acc;   // 8 lanes: 128B coalesced
        __syncthreads();
    }
}

// ---------------------------------------------------------------------------
// K2: out[t,j] = (Y[t] @ QV)[a_j] + bias[j]. 512 thr, 16 rows/CTA, 2 CTA/SM.
// (unchanged from R5: 2 barriers, hoisted matvec, barrier-free epilogue)
// ---------------------------------------------------------------------------
#define K2_OFF_Y    65536
#define K2_OFF_PART (K2_OFF_Y + 8192)
#define K2_OFF_QM   (K2_OFF_PART + 32768)
#define K2_SMEM     (K2_OFF_QM + 8192)

__global__ void __launch_bounds__(512, 2)
k2_out(const float* __restrict__ qv, const int* __restrict__ assign,
       const float* __restrict__ bias, float* __restrict__ out) {
    extern __shared__ char smem[];
    float*  s_qv   = (float*)smem;
    float4* s_y4   = (float4*)(smem + K2_OFF_Y);
    float4* s_part = (float4*)(smem + K2_OFF_PART);
    float4* s_qm   = (float4*)(smem + K2_OFF_QM);

    const int tid  = threadIdx.x;
    const int kout = tid & 127, c = tid >> 7;

    #pragma unroll
    for (int u = 0; u < 8; u++)
        ((float4*)s_qv)[u * 512 + tid] = ((const float4*)qv)[u * 512 + tid];

    const int t0 = blockIdx.x * 16;
    s_y4[tid] = g_Yt[(t0 >> 2) * KB + tid];

    float4 biasr[2]; unsigned ar[2];
    #pragma unroll
    for (int s = 0; s < 2; s++) {
        int e4 = s * 512 + tid;
        biasr[s] = ((const float4*)bias)[e4];
        int4 a = ((const int4*)assign)[e4];
        ar[s] = (unsigned)(a.x & 127)
              | ((unsigned)(a.y & 127) << 8)
              | ((unsigned)(a.z & 127) << 16)
              | ((unsigned)(a.w & 127) << 24);
    }
    __syncthreads();

    unsigned long long acc[8];
    #pragma unroll
    for (int i = 0; i < 8; i++) acc[i] = 0ull;
    const ulonglong2* sy2 = (const ulonglong2*)s_y4;
    #pragma unroll
    for (int i = 0; i < 32; i++) {
        unsigned long long qd = pack2(s_qv[(c * 32 + i) * KB + kout]);
        #pragma unroll
        for (int g = 0; g < 4; g++) {
            ulonglong2 yv = sy2[g * KB + c * 32 + i];
            fma2(acc[2 * g],     yv.x, qd);
            fma2(acc[2 * g + 1], yv.y, qd);
        }
    }
    #pragma unroll
    for (int g = 0; g < 4; g++)
        s_part[g * 512 + c * 128 + kout] = make_float4(
            __uint_as_float((unsigned)acc[2 * g]),
            __uint_as_float((unsigned)(acc[2 * g] >> 32)),
            __uint_as_float((unsigned)acc[2 * g + 1]),
            __uint_as_float((unsigned)(acc[2 * g + 1] >> 32)));
    __syncthreads();

    {
        float4 t = s_part[c * 512 + kout];
        #pragma unroll
        for (int u = 1; u < 4; u++) {
            float4 p = s_part[c * 512 + u * 128 + kout];
            t.x += p.x; t.y += p.y; t.z += p.z; t.w += p.w;
        }
        s_qm[c * KB + kout] = t;
    }
    __syncthreads();

    float4* out4 = (float4*)out;
    #pragma unroll
    for (int g = 0; g < 4; g++) {
        const float4* qm = s_qm + g * KB;
        #pragma unroll
        for (int s = 0; s < 2; s++) {
            unsigned a = ar[s];
            float4 q0 = qm[a & 255];
            float4 q1 = qm[(a >> 8)  & 255];
            float4 q2 = qm[(a >> 16) & 255];
            float4 q3 = qm[a >> 24];
            float4 bb = biasr[s];
            size_t rb = (size_t)(t0 + 4 * g) * 1024 + s * 512 + tid;
            out4[rb]        = make_float4(q0.x + bb.x, q1.x + bb.y, q2.x + bb.z, q3.x + bb.w);
            out4[rb + 1024] = make_float4(q0.y + bb.x, q1.y + bb.y, q2.y + bb.z, q3.y + bb.w);
            out4[rb + 2048] = make_float4(q0.z + bb.x, q1.z + bb.y, q2.z + bb.z, q3.z + bb.w);
            out4[rb + 3072] = make_float4(q0.w + bb.x, q1.w + bb.y, q2.w + bb.z, q3.w + bb.w);
        }
    }
}

extern "C" void kernel_launch(void* const* d_in, const int* in_sizes, int n_in,
                              void* d_out, int out_size) {
    const float* x      = (const float*)d_in[0];
    const float* qv     = (const float*)d_in[1];
    const int*   assign = (const int*)d_in[2];
    const float* bias   = (const float*)d_in[3];
    float*       out    = (float*)d_out;

    (void)cudaFuncSetAttribute(k1_bins,
        cudaFuncAttributeMaxDynamicSharedMemorySize, K1_SMEM);
    (void)cudaFuncSetAttribute(k2_out,
        cudaFuncAttributeMaxDynamicSharedMemorySize, K2_SMEM);

    k0_build<<<KB, 32>>>(assign);
    k1_bins<<<TROWS / 16, 512, K1_SMEM>>>(x);
    k2_out<<<TROWS / 16, 512, K2_SMEM>>>(qv, assign, bias, out);
}